// round 9
// baseline (speedup 1.0000x reference)
#include <cuda_runtime.h>

#define B_  65536
#define T_  28
#define IN_ 28
#define HD_ 28
#define NC_ 10

typedef unsigned long long ull;

__device__ __forceinline__ ull pack2(float lo, float hi) {
    ull r; asm("mov.b64 %0, {%1, %2};" : "=l"(r) : "f"(lo), "f"(hi)); return r;
}
__device__ __forceinline__ void fma2(ull& acc, ull a, ull b) {
    asm("fma.rn.f32x2 %0, %1, %2, %0;" : "+l"(acc) : "l"(a), "l"(b));
}
__device__ __forceinline__ float hadd2(ull v) {
    float lo, hi; asm("mov.b64 {%0, %1}, %2;" : "=f"(lo), "=f"(hi) : "l"(v));
    return lo + hi;
}
__device__ __forceinline__ float tanh_a(float v) {
    float r; asm("tanh.approx.f32 %0, %1;" : "=f"(r) : "f"(v)); return r;
}
__device__ __forceinline__ float sigm(float v) {
    return fmaf(0.5f, tanh_a(0.5f * v), 0.5f);
}

// One LSTM unit, two samples, weights broadcast from smem.
// Gate rows: row, row+nr, row+2nr, row+3nr; each row = [W_k(28) | W_he(4)] (32 floats).
// k0/k1: 14 register pairs (hd or x). heX: pairs 14,15.
__device__ __forceinline__ void lstm_unit_dual(
    const float* __restrict__ sW, int row, int nr,
    const float* __restrict__ sB, int unit,
    const ull* k0, const ull* k1,
    ull heA0, ull heB0, ull heA1, ull heB1,
    float& c0, float& c1, float& h0, float& h1)
{
    ulonglong2 b01 = *(const ulonglong2*)&sB[unit * 8];
    ulonglong2 b23 = *(const ulonglong2*)&sB[unit * 8 + 4];
    ull aI0 = b01.x, aI1 = b01.x;
    ull aF0 = b01.y, aF1 = b01.y;
    ull aG0 = b23.x, aG1 = b23.x;
    ull aO0 = b23.y, aO1 = b23.y;
    const float* wi = sW + (size_t)row * 32;
    const float* wf = wi + (size_t)nr * 32;
    const float* wg = wf + (size_t)nr * 32;
    const float* wo = wg + (size_t)nr * 32;
#pragma unroll
    for (int q = 0; q < 7; ++q) {
        ulonglong2 Wi = *(const ulonglong2*)&wi[q * 4];
        ulonglong2 Wf = *(const ulonglong2*)&wf[q * 4];
        ulonglong2 Wg = *(const ulonglong2*)&wg[q * 4];
        ulonglong2 Wo = *(const ulonglong2*)&wo[q * 4];
        ull kA0 = k0[2*q], kB0 = k0[2*q+1];
        ull kA1 = k1[2*q], kB1 = k1[2*q+1];
        fma2(aI0, Wi.x, kA0); fma2(aI0, Wi.y, kB0);
        fma2(aI1, Wi.x, kA1); fma2(aI1, Wi.y, kB1);
        fma2(aF0, Wf.x, kA0); fma2(aF0, Wf.y, kB0);
        fma2(aF1, Wf.x, kA1); fma2(aF1, Wf.y, kB1);
        fma2(aG0, Wg.x, kA0); fma2(aG0, Wg.y, kB0);
        fma2(aG1, Wg.x, kA1); fma2(aG1, Wg.y, kB1);
        fma2(aO0, Wo.x, kA0); fma2(aO0, Wo.y, kB0);
        fma2(aO1, Wo.x, kA1); fma2(aO1, Wo.y, kB1);
    }
    {   // q = 7: he pairs
        ulonglong2 Wi = *(const ulonglong2*)&wi[28];
        ulonglong2 Wf = *(const ulonglong2*)&wf[28];
        ulonglong2 Wg = *(const ulonglong2*)&wg[28];
        ulonglong2 Wo = *(const ulonglong2*)&wo[28];
        fma2(aI0, Wi.x, heA0); fma2(aI0, Wi.y, heB0);
        fma2(aI1, Wi.x, heA1); fma2(aI1, Wi.y, heB1);
        fma2(aF0, Wf.x, heA0); fma2(aF0, Wf.y, heB0);
        fma2(aF1, Wf.x, heA1); fma2(aF1, Wf.y, heB1);
        fma2(aG0, Wg.x, heA0); fma2(aG0, Wg.y, heB0);
        fma2(aG1, Wg.x, heA1); fma2(aG1, Wg.y, heB1);
        fma2(aO0, Wo.x, heA0); fma2(aO0, Wo.y, heB0);
        fma2(aO1, Wo.x, heA1); fma2(aO1, Wo.y, heB1);
    }
    {
        float gi = sigm(hadd2(aI0)), gf = sigm(hadd2(aF0));
        float gg = tanh_a(hadd2(aG0)), go = sigm(hadd2(aO0));
        float c = gf * c0 + gi * gg; c0 = c; h0 = go * tanh_a(c);
    }
    {
        float gi = sigm(hadd2(aI1)), gf = sigm(hadd2(aF1));
        float gg = tanh_a(hadd2(aG1)), go = sigm(hadd2(aO1));
        float c = gf * c1 + gi * gg; c1 = c; h1 = go * tanh_a(c);
    }
}

// block = 128 thr = 4 warps; each LANE owns 2 samples -> 256 samples/CTA, 256 CTAs.
__global__ void __launch_bounds__(128, 2)
ae_lstm_kernel(const float* __restrict__ x,
               const float* __restrict__ eWih, const float* __restrict__ eWhh,
               const float* __restrict__ eb,
               const float* __restrict__ dWih, const float* __restrict__ dWhh,
               const float* __restrict__ db,
               const float* __restrict__ uW,  const float* __restrict__ ubv,
               float* __restrict__ out, float* __restrict__ pred)
{
    __shared__ __align__(16) float sWd[112 * 32];   // [Whh(28)|Wih(4)] per gate row
    __shared__ __align__(16) float sWe[16 * 32];    // [Wih(28)|Whh(4)]
    __shared__ __align__(16) float sBd[28 * 8];     // (bi,0,bf,0,bg,0,bo,0) per unit
    __shared__ __align__(16) float sBe[4 * 8];
    __shared__ __align__(16) float sU[NC_ * 32];    // [U(28)|ub|pad]
    __shared__ __align__(16) float hbuf[4][64 * 28];

    const int tid = threadIdx.x;
    for (int i = tid; i < 112 * 32; i += 128) {
        int row = i >> 5, c = i & 31;
        sWd[i] = (c < 28) ? dWhh[row * 28 + c] : dWih[row * 4 + (c - 28)];
    }
    for (int i = tid; i < 16 * 32; i += 128) {
        int row = i >> 5, c = i & 31;
        sWe[i] = (c < 28) ? eWih[row * 28 + c] : eWhh[row * 4 + (c - 28)];
    }
    for (int i = tid; i < 28 * 8; i += 128) {
        int unit = i >> 3, q = i & 7;
        sBd[i] = (q & 1) ? 0.f : db[(q >> 1) * 28 + unit];
    }
    for (int i = tid; i < 4 * 8; i += 128) {
        int unit = i >> 3, q = i & 7;
        sBe[i] = (q & 1) ? 0.f : eb[(q >> 1) * 4 + unit];
    }
    for (int i = tid; i < NC_ * 32; i += 128) {
        int k = i >> 5, c = i & 31;
        sU[i] = (c < 28) ? uW[k * 28 + c] : ((c == 28) ? ubv[k] : 0.f);
    }
    __syncthreads();

    const int lane = tid & 31;
    const int w    = tid >> 5;
    const int s0   = blockIdx.x * 256 + w * 64 + lane;
    const int s1   = s0 + 32;

    const float* xg0 = x + (size_t)s0 * (T_ * IN_);
    const float* xg1 = x + (size_t)s1 * (T_ * IN_);
    float*       og0 = out + (size_t)s0 * (T_ * HD_);
    float*       og1 = out + (size_t)s1 * (T_ * HD_);
    float* hb0 = &hbuf[w][lane * 28];
    float* hb1 = &hbuf[w][(lane + 32) * 28];

    // ---------- lane-local state ----------
    ull   hd0[14], hd1[14];
    float cd0[28], cd1[28];
    ull   he0[2] = {0ull, 0ull}, he1[2] = {0ull, 0ull};
    float ce0[4] = {0,0,0,0}, ce1[4] = {0,0,0,0};
#pragma unroll
    for (int q = 0; q < 14; ++q) { hd0[q] = 0ull; hd1[q] = 0ull; }
#pragma unroll
    for (int j = 0; j < 28; ++j) { cd0[j] = 0.f; cd1[j] = 0.f; }

    // x(0) into registers
    ull xn0[14], xn1[14];
#pragma unroll
    for (int q = 0; q < 7; ++q) {
        ulonglong2 v0 = __ldg((const ulonglong2*)xg0 + q);
        ulonglong2 v1 = __ldg((const ulonglong2*)xg1 + q);
        xn0[2*q] = v0.x; xn0[2*q+1] = v0.y;
        xn1[2*q] = v1.x; xn1[2*q+1] = v1.y;
    }

#pragma unroll 1
    for (int t = 0; t < T_; ++t) {
        // ===== encoder(t): 4 units, k = [x(t) | he] =====
        float hen0[4], hen1[4];
#pragma unroll
        for (int e = 0; e < 4; ++e)
            lstm_unit_dual(sWe, e, 4, sBe, e, xn0, xn1,
                           he0[0], he0[1], he1[0], he1[1],
                           ce0[e], ce1[e], hen0[e], hen1[e]);
        he0[0] = pack2(hen0[0], hen0[1]); he0[1] = pack2(hen0[2], hen0[3]);
        he1[0] = pack2(hen1[0], hen1[1]); he1[1] = pack2(hen1[2], hen1[3]);

        // ===== prefetch x(t+1); consumed next iteration (hidden under decoder) =====
        if (t + 1 < T_) {
#pragma unroll
            for (int q = 0; q < 7; ++q) {
                ulonglong2 v0 = __ldg((const ulonglong2*)(xg0 + (t+1) * IN_) + q);
                ulonglong2 v1 = __ldg((const ulonglong2*)(xg1 + (t+1) * IN_) + q);
                xn0[2*q] = v0.x; xn0[2*q+1] = v0.y;
                xn1[2*q] = v1.x; xn1[2*q+1] = v1.y;
            }
        }

        // ===== decoder(t): 28 units, k = [hd(t-1) | he(t)] =====
        float hp0, hp1;
#pragma unroll
        for (int j = 0; j < 28; ++j) {
            float h0, h1;
            lstm_unit_dual(sWd, j, 28, sBd, j, hd0, hd1,
                           he0[0], he0[1], he1[0], he1[1],
                           cd0[j], cd1[j], h0, h1);
            if (j & 1) {
                ull p0 = pack2(hp0, h0);
                ull p1 = pack2(hp1, h1);
                *(ull*)(og0 + t * HD_ + (j - 1)) = p0;
                *(ull*)(og1 + t * HD_ + (j - 1)) = p1;
                *(ull*)(hb0 + (j - 1)) = p0;     // lane-private slot, no sync needed
                *(ull*)(hb1 + (j - 1)) = p1;
            } else { hp0 = h0; hp1 = h1; }
        }
        // reload hd(t) (lane-private smem round-trip breaks RAW on hd regs)
#pragma unroll
        for (int q = 0; q < 14; ++q) {
            hd0[q] = *(const ull*)(hb0 + 2 * q);
            hd1[q] = *(const ull*)(hb1 + 2 * q);
        }
    }

    // ===== classifier + softmax, lane-local for both samples =====
#pragma unroll
    for (int s = 0; s < 2; ++s) {
        const ull* hd = s ? hd1 : hd0;
        float lg[NC_];
        float mx = -3.4e38f;
#pragma unroll
        for (int k = 0; k < NC_; ++k) {
            ull a = pack2(sU[k * 32 + 28], 0.f);
#pragma unroll
            for (int m = 0; m < 14; ++m)
                fma2(a, *(const ull*)&sU[k * 32 + 2 * m], hd[m]);
            lg[k] = hadd2(a);
            mx = fmaxf(mx, lg[k]);
        }
        float sum = 0.f;
#pragma unroll
        for (int k = 0; k < NC_; ++k) { float e = __expf(lg[k] - mx); lg[k] = e; sum += e; }
        float inv = __fdividef(1.0f, sum);
        float2* pp = (float2*)(pred + (size_t)(s ? s1 : s0) * NC_);
#pragma unroll
        for (int k = 0; k < 5; ++k)
            pp[k] = make_float2(lg[2*k] * inv, lg[2*k+1] * inv);
    }
}

extern "C" void kernel_launch(void* const* d_in, const int* in_sizes, int n_in,
                              void* d_out, int out_size)
{
    const float* x    = (const float*)d_in[0];
    const float* eWih = (const float*)d_in[1];
    const float* eWhh = (const float*)d_in[2];
    const float* eb   = (const float*)d_in[3];
    const float* dWih = (const float*)d_in[4];
    const float* dWhh = (const float*)d_in[5];
    const float* db   = (const float*)d_in[6];
    const float* uW   = (const float*)d_in[7];
    const float* ub   = (const float*)d_in[8];

    float* out  = (float*)d_out;                 // [B, T, 28]
    float* pred = out + (size_t)B_ * T_ * HD_;   // [1, B, 10]

    dim3 grid(B_ / 256), block(128);             // 2 samples per lane
    ae_lstm_kernel<<<grid, block>>>(x, eWih, eWhh, eb, dWih, dWhh, db, uW, ub,
                                    out, pred);
}

// round 10
// speedup vs baseline: 1.1013x; 1.1013x over previous
#include <cuda_runtime.h>

#define B_  65536
#define T_  28
#define IN_ 28
#define HD_ 28
#define NC_ 10

typedef unsigned long long ull;

__device__ __forceinline__ ull pack2(float lo, float hi) {
    ull r; asm("mov.b64 %0, {%1, %2};" : "=l"(r) : "f"(lo), "f"(hi)); return r;
}
__device__ __forceinline__ void fma2(ull& acc, ull a, ull b) {
    asm("fma.rn.f32x2 %0, %1, %2, %0;" : "+l"(acc) : "l"(a), "l"(b));
}
__device__ __forceinline__ float hadd2(ull v) {
    float lo, hi; asm("mov.b64 {%0, %1}, %2;" : "=f"(lo), "=f"(hi) : "l"(v));
    return lo + hi;
}
__device__ __forceinline__ float tanh_a(float v) {
    float r; asm("tanh.approx.f32 %0, %1;" : "=f"(r) : "f"(v)); return r;
}
__device__ __forceinline__ float sigm(float v) {
    return fmaf(0.5f, tanh_a(0.5f * v), 0.5f);
}

// One LSTM unit, two samples, weights broadcast from smem.
// Gate rows at row, row+nr, row+2nr, row+3nr; each row = [W_k(28)|W_he(4)] (32 floats).
__device__ __forceinline__ void lstm_unit_dual(
    const float* __restrict__ sW, int row, int nr,
    const float* __restrict__ sB, int unit,
    const ull* k0, const ull* k1,
    ull heA0, ull heB0, ull heA1, ull heB1,
    float& c0, float& c1, float& h0, float& h1)
{
    float4 bb = *(const float4*)&sB[unit * 4];   // bi, bf, bg, bo
    ull aI0 = pack2(bb.x, 0.f), aI1 = aI0;
    ull aF0 = pack2(bb.y, 0.f), aF1 = aF0;
    ull aG0 = pack2(bb.z, 0.f), aG1 = aG0;
    ull aO0 = pack2(bb.w, 0.f), aO1 = aO0;
    const float* wi = sW + (size_t)row * 32;
    const float* wf = wi + (size_t)nr * 32;
    const float* wg = wf + (size_t)nr * 32;
    const float* wo = wg + (size_t)nr * 32;
#pragma unroll
    for (int q = 0; q < 7; ++q) {
        ulonglong2 Wi = *(const ulonglong2*)&wi[q * 4];
        ulonglong2 Wf = *(const ulonglong2*)&wf[q * 4];
        ulonglong2 Wg = *(const ulonglong2*)&wg[q * 4];
        ulonglong2 Wo = *(const ulonglong2*)&wo[q * 4];
        ull kA0 = k0[2*q], kB0 = k0[2*q+1];
        ull kA1 = k1[2*q], kB1 = k1[2*q+1];
        fma2(aI0, Wi.x, kA0); fma2(aI0, Wi.y, kB0);
        fma2(aI1, Wi.x, kA1); fma2(aI1, Wi.y, kB1);
        fma2(aF0, Wf.x, kA0); fma2(aF0, Wf.y, kB0);
        fma2(aF1, Wf.x, kA1); fma2(aF1, Wf.y, kB1);
        fma2(aG0, Wg.x, kA0); fma2(aG0, Wg.y, kB0);
        fma2(aG1, Wg.x, kA1); fma2(aG1, Wg.y, kB1);
        fma2(aO0, Wo.x, kA0); fma2(aO0, Wo.y, kB0);
        fma2(aO1, Wo.x, kA1); fma2(aO1, Wo.y, kB1);
    }
    {   // he pairs (columns 28..31)
        ulonglong2 Wi = *(const ulonglong2*)&wi[28];
        ulonglong2 Wf = *(const ulonglong2*)&wf[28];
        ulonglong2 Wg = *(const ulonglong2*)&wg[28];
        ulonglong2 Wo = *(const ulonglong2*)&wo[28];
        fma2(aI0, Wi.x, heA0); fma2(aI0, Wi.y, heB0);
        fma2(aI1, Wi.x, heA1); fma2(aI1, Wi.y, heB1);
        fma2(aF0, Wf.x, heA0); fma2(aF0, Wf.y, heB0);
        fma2(aF1, Wf.x, heA1); fma2(aF1, Wf.y, heB1);
        fma2(aG0, Wg.x, heA0); fma2(aG0, Wg.y, heB0);
        fma2(aG1, Wg.x, heA1); fma2(aG1, Wg.y, heB1);
        fma2(aO0, Wo.x, heA0); fma2(aO0, Wo.y, heB0);
        fma2(aO1, Wo.x, heA1); fma2(aO1, Wo.y, heB1);
    }
    {
        float gi = sigm(hadd2(aI0)), gf = sigm(hadd2(aF0));
        float gg = tanh_a(hadd2(aG0)), go = sigm(hadd2(aO0));
        float c = gf * c0 + gi * gg; c0 = c; h0 = go * tanh_a(c);
    }
    {
        float gi = sigm(hadd2(aI1)), gf = sigm(hadd2(aF1));
        float gg = tanh_a(hadd2(aG1)), go = sigm(hadd2(aO1));
        float c = gf * c1 + gi * gg; c1 = c; h1 = go * tanh_a(c);
    }
}

// block = 64 thr = 2 warps; each LANE owns 2 samples -> 128 samples/CTA, grid 512.
__global__ void __launch_bounds__(64, 4)
ae_lstm_kernel(const float* __restrict__ x,
               const float* __restrict__ eWih, const float* __restrict__ eWhh,
               const float* __restrict__ eb,
               const float* __restrict__ dWih, const float* __restrict__ dWhh,
               const float* __restrict__ db,
               const float* __restrict__ uW,  const float* __restrict__ ubv,
               float* __restrict__ out, float* __restrict__ pred)
{
    __shared__ __align__(16) float sWd[112 * 32];   // 14336 B
    __shared__ __align__(16) float sWe[16 * 32];    //  2048 B
    __shared__ __align__(16) float sBd[28 * 4];     //   448 B (bi,bf,bg,bo)
    __shared__ __align__(16) float sBe[4 * 4];      //    64 B
    __shared__ __align__(16) float sU[NC_ * 30];    //  1200 B  [U(28)|ub|pad]
    __shared__ __align__(16) ull   xsu[2][14 * 64]; // 14336 B  pair-interleaved x
    __shared__ __align__(16) ull   hsu[2][14 * 64]; // 14336 B  pair-interleaved h

    const int tid = threadIdx.x;
    for (int i = tid; i < 112 * 32; i += 64) {
        int row = i >> 5, c = i & 31;
        sWd[i] = (c < 28) ? dWhh[row * 28 + c] : dWih[row * 4 + (c - 28)];
    }
    for (int i = tid; i < 16 * 32; i += 64) {
        int row = i >> 5, c = i & 31;
        sWe[i] = (c < 28) ? eWih[row * 28 + c] : eWhh[row * 4 + (c - 28)];
    }
    for (int i = tid; i < 112; i += 64) {
        int unit = i >> 2, g = i & 3;
        sBd[i] = db[g * 28 + unit];
    }
    if (tid < 16) {
        int unit = tid >> 2, g = tid & 3;
        sBe[tid] = eb[g * 4 + unit];
    }
    for (int i = tid; i < NC_ * 30; i += 64) {
        int k = i / 30, c = i % 30;
        sU[i] = (c < 28) ? uW[k * 28 + c] : ((c == 28) ? ubv[k] : 0.f);
    }
    __syncthreads();

    const int lane = tid & 31;
    const int w    = tid >> 5;
    const int s0   = blockIdx.x * 128 + w * 64 + lane;
    const int s1   = s0 + 32;

    const float* xg0 = x + (size_t)s0 * (T_ * IN_);
    const float* xg1 = x + (size_t)s1 * (T_ * IN_);
    float*       og0 = out + (size_t)s0 * (T_ * HD_);
    float*       og1 = out + (size_t)s1 * (T_ * HD_);
    ull* xw = xsu[w];
    ull* hw = hsu[w];

    // ---------- lane-local state ----------
    ull   hd0[14], hd1[14];
    float cd0[28], cd1[28];
    ull   he0[2] = {0ull, 0ull}, he1[2] = {0ull, 0ull};
    float ce0[4] = {0,0,0,0}, ce1[4] = {0,0,0,0};
#pragma unroll
    for (int q = 0; q < 14; ++q) { hd0[q] = 0ull; hd1[q] = 0ull; }
#pragma unroll
    for (int j = 0; j < 28; ++j) { cd0[j] = 0.f; cd1[j] = 0.f; }

    // ---------- stage x(0) into xs (lane-private rows; no sync needed) ----------
#pragma unroll
    for (int q = 0; q < 7; ++q) {
        ulonglong2 v0 = __ldg((const ulonglong2*)xg0 + q);
        ulonglong2 v1 = __ldg((const ulonglong2*)xg1 + q);
        xw[(2*q) * 64 + lane]        = v0.x;
        xw[(2*q+1) * 64 + lane]      = v0.y;
        xw[(2*q) * 64 + lane + 32]   = v1.x;
        xw[(2*q+1) * 64 + lane + 32] = v1.y;
    }

#pragma unroll 1
    for (int t = 0; t < T_; ++t) {
        // ===== load x(t) pairs from smem (scoped transients) =====
        ull xp0[14], xp1[14];
#pragma unroll
        for (int q = 0; q < 14; ++q) {
            xp0[q] = xw[q * 64 + lane];
            xp1[q] = xw[q * 64 + lane + 32];
        }

        // ===== encoder(t): 4 units =====
        float hen0[4], hen1[4];
#pragma unroll
        for (int e = 0; e < 4; ++e)
            lstm_unit_dual(sWe, e, 4, sBe, e, xp0, xp1,
                           he0[0], he0[1], he1[0], he1[1],
                           ce0[e], ce1[e], hen0[e], hen1[e]);
        he0[0] = pack2(hen0[0], hen0[1]); he0[1] = pack2(hen0[2], hen0[3]);
        he1[0] = pack2(hen1[0], hen1[1]); he1[1] = pack2(hen1[2], hen1[3]);

        // ===== prefetch x(t+1) -> xs (xp dead; single-buffer safe) =====
        if (t + 1 < T_) {
            ulonglong2 a0[7], a1[7];
#pragma unroll
            for (int q = 0; q < 7; ++q) {
                a0[q] = __ldg((const ulonglong2*)(xg0 + (t+1) * IN_) + q);
                a1[q] = __ldg((const ulonglong2*)(xg1 + (t+1) * IN_) + q);
            }
#pragma unroll
            for (int q = 0; q < 7; ++q) {
                xw[(2*q) * 64 + lane]        = a0[q].x;
                xw[(2*q+1) * 64 + lane]      = a0[q].y;
                xw[(2*q) * 64 + lane + 32]   = a1[q].x;
                xw[(2*q+1) * 64 + lane + 32] = a1[q].y;
            }
        }

        // ===== decoder(t): 28 units, k = [hd(t-1)|he(t)] =====
        float hp0, hp1;
#pragma unroll
        for (int j = 0; j < 28; ++j) {
            float h0, h1;
            lstm_unit_dual(sWd, j, 28, sBd, j, hd0, hd1,
                           he0[0], he0[1], he1[0], he1[1],
                           cd0[j], cd1[j], h0, h1);
            if (j & 1) {
                ull p0 = pack2(hp0, h0);
                ull p1 = pack2(hp1, h1);
                *(ull*)(og0 + t * HD_ + (j - 1)) = p0;
                *(ull*)(og1 + t * HD_ + (j - 1)) = p1;
                hw[(j >> 1) * 64 + lane]      = p0;   // lane-private slot
                hw[(j >> 1) * 64 + lane + 32] = p1;
            } else { hp0 = h0; hp1 = h1; }
        }
        // reload hd(t) (smem round-trip avoids +56 live regs)
#pragma unroll
        for (int q = 0; q < 14; ++q) {
            hd0[q] = hw[q * 64 + lane];
            hd1[q] = hw[q * 64 + lane + 32];
        }
    }

    // ===== classifier + softmax, lane-local for both samples =====
#pragma unroll
    for (int s = 0; s < 2; ++s) {
        const ull* hd = s ? hd1 : hd0;
        float lg[NC_];
        float mx = -3.4e38f;
#pragma unroll
        for (int k = 0; k < NC_; ++k) {
            ull a = pack2(sU[k * 30 + 28], 0.f);
#pragma unroll
            for (int m = 0; m < 14; ++m)
                fma2(a, *(const ull*)&sU[k * 30 + 2 * m], hd[m]);
            lg[k] = hadd2(a);
            mx = fmaxf(mx, lg[k]);
        }
        float sum = 0.f;
#pragma unroll
        for (int k = 0; k < NC_; ++k) { float e = __expf(lg[k] - mx); lg[k] = e; sum += e; }
        float inv = __fdividef(1.0f, sum);
        float2* pp = (float2*)(pred + (size_t)(s ? s1 : s0) * NC_);
#pragma unroll
        for (int k = 0; k < 5; ++k)
            pp[k] = make_float2(lg[2*k] * inv, lg[2*k+1] * inv);
    }
}

extern "C" void kernel_launch(void* const* d_in, const int* in_sizes, int n_in,
                              void* d_out, int out_size)
{
    const float* x    = (const float*)d_in[0];
    const float* eWih = (const float*)d_in[1];
    const float* eWhh = (const float*)d_in[2];
    const float* eb   = (const float*)d_in[3];
    const float* dWih = (const float*)d_in[4];
    const float* dWhh = (const float*)d_in[5];
    const float* db   = (const float*)d_in[6];
    const float* uW   = (const float*)d_in[7];
    const float* ub   = (const float*)d_in[8];

    float* out  = (float*)d_out;                 // [B, T, 28]
    float* pred = out + (size_t)B_ * T_ * HD_;   // [1, B, 10]

    dim3 grid(B_ / 128), block(64);              // 2 samples per lane, 512 CTAs
    ae_lstm_kernel<<<grid, block>>>(x, eWih, eWhh, eb, dWih, dWhh, db, uW, ub,
                                    out, pred);
}